// round 1
// baseline (speedup 1.0000x reference)
#include <cuda_runtime.h>

#define B_   8
#define H_   1024
#define W_   1024
#define NW_  32                      // 32-bit words per column (H/32)
#define NPIX (B_ * H_ * W_)

// Scratch: column-major-in-rows bit masks: [b][word_row][j], 1 MB total.
__device__ unsigned int g_bits[B_ * NW_ * W_];
__device__ unsigned int g_spos;
__device__ double       g_acc;

// ---------------------------------------------------------------------------
// 0) zero the accumulators (must run each graph replay)
// ---------------------------------------------------------------------------
__global__ void bg_init_kernel() {
    g_spos = 0u;
    g_acc  = 0.0;
}

// ---------------------------------------------------------------------------
// 1) pack targets>0.5 into per-column bitmasks + count foreground pixels.
//    One thread per (b, word_row, j): reads 32 rows (coalesced across warp).
// ---------------------------------------------------------------------------
__global__ void bg_pack_kernel(const float* __restrict__ targets) {
    int tid = blockIdx.x * blockDim.x + threadIdx.x;   // 0 .. B_*NW_*W_-1
    int j   = tid & (W_ - 1);
    int wr  = (tid >> 10) & 31;
    int b   = tid >> 15;

    const float* col = targets + ((size_t)(b * H_ + wr * 32)) * W_ + j;
    unsigned int bits = 0u;
#pragma unroll
    for (int k = 0; k < 32; ++k) {
        if (col[(size_t)k * W_] > 0.5f) bits |= (1u << k);
    }
    g_bits[tid] = bits;

    // block-level popcount reduction -> one atomic per block
    int c = __popc(bits);
#pragma unroll
    for (int off = 16; off; off >>= 1)
        c += __shfl_down_sync(0xffffffffu, c, off);

    __shared__ int ssum[8];
    int lane = threadIdx.x & 31, w = threadIdx.x >> 5;
    if (lane == 0) ssum[w] = c;
    __syncthreads();
    if (threadIdx.x < 8) {
        int v = ssum[threadIdx.x];
#pragma unroll
        for (int off = 4; off; off >>= 1)
            v += __shfl_down_sync(0xffu, v, off);
        if (threadIdx.x == 0) atomicAdd(&g_spos, (unsigned int)v);
    }
}

// ---------------------------------------------------------------------------
// 2) per-row block: vertical truncated distance from bitmasks (clz/ffs on a
//    65-bit window), then adaptive horizontal pass for exact truncated d^2,
//    then fused loss, block-reduced into a double accumulator.
// ---------------------------------------------------------------------------
__global__ void __launch_bounds__(256) bg_loss_kernel(const float* __restrict__ probs) {
    __shared__ int   s_gsq[W_ + 64];   // [32 pad | 1024 | 32 pad], pad = 1024 (= R^2)
    __shared__ float s_red[256];

    const int bi = blockIdx.x;         // b*H + i
    const int b  = bi >> 10;
    const int i  = bi & 1023;
    const int wi = i >> 5;             // word row
    const int k  = i & 31;             // bit within word
    const int t  = threadIdx.x;

    if (t < 64) {
        int idx = (t < 32) ? t : (W_ + 32 + (t - 32));
        s_gsq[idx] = 1024;
    }

    const unsigned int* wbase = g_bits + (size_t)b * NW_ * W_;

#pragma unroll
    for (int q = 0; q < 4; ++q) {
        int j = t + q * 256;
        unsigned int w0 = (wi > 0)        ? wbase[(wi - 1) * W_ + j] : 0u;
        unsigned int w1 =                   wbase[ wi      * W_ + j];
        unsigned int w2 = (wi < NW_ - 1)  ? wbase[(wi + 1) * W_ + j] : 0u;

        // rows [i-32 .. i+32] window
        unsigned long long clo = (((unsigned long long)w1) << 32) | (unsigned long long)w0;
        unsigned long long chi = (((unsigned long long)w2) << 32) | (unsigned long long)w1;
        unsigned int       u   = (unsigned int)(clo >> k);              // rows i-32..i-1 (bit t' = row i-32+t')
        unsigned long long v   = (chi >> k) & 0x1FFFFFFFFull;           // rows i..i+32

        int du = __clz((int)u) + 1;                 // 33 if none above
        int f  = __ffsll((long long)v);
        int dd = f ? (f - 1) : 33;                  // 0 if fg at (i,j)
        int g  = min(min(du, dd), 32);
        s_gsq[32 + j] = g * g;
    }
    __syncthreads();

    // global class weights
    float Sp    = (float)g_spos;
    float Sn    = (float)NPIX - Sp;
    float w_pos = fminf((Sn + 1e-6f) / (Sp + 1e-6f), 1.0f);
    float baseN = (Sp + 1e-6f) / (Sn + 1e-6f);

    const float* prow = probs + (size_t)bi * W_;
    float acc = 0.0f;

#pragma unroll
    for (int q = 0; q < 4; ++q) {
        int j = t + q * 256;
        const int* gp = s_gsq + 32 + j;

        float p = prow[j];
        p = fminf(fmaxf(p, 1e-6f), 1.0f - 1e-6f);

        int best = gp[0];                 // o = 0 term; 0 <=> fg pixel (y=1)
        if (best == 0) {
            acc += w_pos * (-__logf(p));
        } else {
            // adaptive exact truncated horizontal min: stop when o^2 >= best
#pragma unroll 1
            for (int o = 1; o * o < best; ++o) {
                int c = o * o;
                best = min(best, gp[-o] + c);
                best = min(best, gp[ o] + c);
            }
            float wb = __expf(-(float)best * 0.125f);     // exp(-d^2 / (2*sigma^2)), sigma=2
            float wn = fminf(baseN + wb, 1.0f);
            acc += wn * (-__logf(1.0f - p));
        }
    }

    // block reduction -> one double atomic per block
    s_red[t] = acc;
    __syncthreads();
#pragma unroll
    for (int s = 128; s > 0; s >>= 1) {
        if (t < s) s_red[t] += s_red[t + s];
        __syncthreads();
    }
    if (t == 0) atomicAdd(&g_acc, (double)s_red[0]);
}

// ---------------------------------------------------------------------------
// 3) finalize: mean
// ---------------------------------------------------------------------------
__global__ void bg_finalize_kernel(float* __restrict__ out) {
    out[0] = (float)(g_acc * (1.0 / (double)NPIX));
}

extern "C" void kernel_launch(void* const* d_in, const int* in_sizes, int n_in,
                              void* d_out, int out_size) {
    const float* probs   = (const float*)d_in[0];
    const float* targets = (const float*)d_in[1];
    float*       out     = (float*)d_out;

    bg_init_kernel<<<1, 1>>>();
    bg_pack_kernel<<<(B_ * NW_ * W_) / 256, 256>>>(targets);
    bg_loss_kernel<<<B_ * H_, 256>>>(probs);
    bg_finalize_kernel<<<1, 1>>>(out);
}